// round 6
// baseline (speedup 1.0000x reference)
#include <cuda_runtime.h>
#include <cstdint>

// HOSVD aggregator, restructured:
//   ris[n,d,r]   = sum_i x[n,d,i] * U_stack[d,i,r]                       (kernel 1)
//   w[n,k]       = ris3[a2]*ris2[a3]*ris1[a4],  k = a2*64+a3*8+a4        (kernel 2)
//   T[n,a0,a1]   = sum_k w[n,k] * G[a0,a1,a2,a3,a4]                      (kernel 2, core, packed f32x2)
//   s[n,a1]      = sum_a0 T[n,a0,a1] * ris0[a0]                          (kernel 2)
//   out[n,o]     = sum_a1 s[n,a1] * U_output[a1,o]                       (kernel 2)

#define TILE    32
#define THREADS 256
#define MAX_N   50016   // 1563 tiles of 32

// ---------------- scratch (no allocations allowed) ----------------
__device__ float g_ris[MAX_N * 32];

// packed fp32x2 FMA: acc = a*b + acc (elementwise on 2 packed floats)
#define FMA_F32X2(acc, a, b) \
    asm("fma.rn.f32x2 %0, %1, %2, %0;" : "+l"(acc) : "l"(a), "l"(b))

// ---------------- kernel 1: ris projection ----------------
// smem: Xs[32*1024] floats, UsT[4*8 rows][260] (padded, transposed U)
#define K1_XS  0
#define K1_UST 32768
#define K1_SMEM_FLOATS (32768 + 32 * 260)   // 41088 floats = 164352 B

__global__ void __launch_bounds__(THREADS, 1)
ris_kernel(const float* __restrict__ x, const float* __restrict__ Ustack, int n)
{
    extern __shared__ float sm1[];
    float* Xs  = sm1 + K1_XS;
    float* UsT = sm1 + K1_UST;
    const int t = threadIdx.x;

    // stage U_stack transposed: UsT[(d*8+r)*260 + i] = U_stack[d][i][r]
    for (int idx = t; idx < 8192; idx += THREADS) {
        int d = idx >> 11;
        int i = (idx >> 3) & 255;
        int r = idx & 7;
        UsT[(d * 8 + r) * 260 + i] = Ustack[idx];
    }

    const int base = blockIdx.x * TILE;
    const float4* xg = reinterpret_cast<const float4*>(x) + (size_t)base * 256;
    float4* Xs4 = reinterpret_cast<float4*>(Xs);
    if (base + TILE <= n) {
        for (int idx = t; idx < 8192; idx += THREADS) Xs4[idx] = xg[idx];
    } else {
        for (int idx = t; idx < 8192; idx += THREADS) {
            int node = base + (idx >> 8);
            Xs4[idx] = (node < n) ? xg[idx] : make_float4(0.f, 0.f, 0.f, 0.f);
        }
    }
    __syncthreads();

    const int nl = t >> 3, r = t & 7;
    const int node = base + nl;
    #pragma unroll
    for (int d = 0; d < 4; ++d) {
        const float* xr = Xs + nl * 1024 + d * 256;
        const float* ur = UsT + (d * 8 + r) * 260;
        float a0 = 0.f, a1 = 0.f, a2 = 0.f, a3 = 0.f;
        #pragma unroll 8
        for (int i = 0; i < 256; i += 4) {
            float4 xv = *reinterpret_cast<const float4*>(xr + i);
            float4 uv = *reinterpret_cast<const float4*>(ur + i);
            a0 = fmaf(xv.x, uv.x, a0);
            a1 = fmaf(xv.y, uv.y, a1);
            a2 = fmaf(xv.z, uv.z, a2);
            a3 = fmaf(xv.w, uv.w, a3);
        }
        if (node < n) g_ris[node * 32 + d * 8 + r] = (a0 + a1) + (a2 + a3);
    }
}

// ---------------- kernel 2: core contraction (persistent) ----------------
// G stored TRANSPOSED: Gs[j][k], j = a0*8+a1 (64 rows), k (512 cols), stride 524.
// Stride 524: 16B-aligned rows (524*4 % 16 == 0); LDS.128 bank-map (j*12+k)%32
// tiles all 32 banks within each 8-lane phase -> conflict-free.
#define GSTRIDE 524
#define GS_OFF 0                          // Gs[64][524] = 33536 floats
#define WS_OFF 33536                      // wS[k][32], 16384 floats (16B-aligned)
#define RT_OFF (33536 + 16384)            // rT[dr][33], 1056
#define UO_OFF (RT_OFF + 1056)            // Uos[8][128], 1024
#define TS_OFF (UO_OFF + 1024)            // Ts[n_local*64 + j], 2048
#define SS_OFF (TS_OFF + 2048)            // ss[n_local*9 + a1], 288
#define K2_SMEM_FLOATS (SS_OFF + 288)     // 54336 floats = 217344 B

__global__ void __launch_bounds__(THREADS, 1)
core_kernel(const float* __restrict__ G, const float* __restrict__ Uout,
            float* __restrict__ out, int n, int ntiles)
{
    extern __shared__ float sm2[];
    float* Gs  = sm2 + GS_OFF;
    float* wS  = sm2 + WS_OFF;
    float* rT  = sm2 + RT_OFF;
    float* Uos = sm2 + UO_OFF;
    float* Ts  = sm2 + TS_OFF;
    float* ss  = sm2 + SS_OFF;

    const int t = threadIdx.x;
    const int warp = t >> 5, lane = t & 31;

    // one-time: permute G into Gs[j*GSTRIDE + k]; copy U_output
    for (int idx = t; idx < 32768; idx += THREADS) {
        float v = G[idx];
        int j = ((idx >> 12) << 3) | ((idx >> 9) & 7);   // a0*8 + a1
        int k = idx & 511;                               // a2*64 + a3*8 + a4
        Gs[j * GSTRIDE + k] = v;
    }
    for (int idx = t; idx < 1024; idx += THREADS) Uos[idx] = Uout[idx];
    __syncthreads();

    // core mapping: warp -> (ng = warp>>1 : 8 nodes, jg = warp&1 : 32 j's)
    const int jg = warp & 1;           // j-half
    const int ng = warp >> 1;          // node-group (8 nodes)
    const int j  = jg * 32 + lane;     // this thread's j = a0*8+a1
    const float* grow = Gs + j * GSTRIDE;

    for (int tile = blockIdx.x; tile < ntiles; tile += gridDim.x) {
        const int base = tile * TILE;

        // load ris tile, transposed: rT[dr][node_local], padded stride 33
        for (int idx = t; idx < 1024; idx += THREADS) {
            int node = idx >> 5;
            int dr   = idx & 31;
            float v = (base + node < n) ? g_ris[(size_t)base * 32 + idx] : 0.f;
            rT[dr * 33 + node] = v;
        }
        __syncthreads();

        // build w: thread -> (nl = t&31, a2 = t>>5); writes coalesced (nl across lanes)
        {
            const int nl = t & 31, a2 = t >> 5;
            float r1v[8];
            #pragma unroll
            for (int a4 = 0; a4 < 8; ++a4) r1v[a4] = rT[(8 + a4) * 33 + nl];
            const float r3 = rT[(24 + a2) * 33 + nl];
            #pragma unroll
            for (int a3 = 0; a3 < 8; ++a3) {
                float p = r3 * rT[(16 + a3) * 33 + nl];
                #pragma unroll
                for (int a4 = 0; a4 < 8; ++a4) {
                    wS[(a2 * 64 + a3 * 8 + a4) * 32 + nl] = p * r1v[a4];
                }
            }
        }
        __syncthreads();

        // ---- core: packed f32x2. Thread: 1 j, 8 nodes (4 packed pairs).
        //      g loaded 4-per-LDS.128 from transposed Gs (software-pipelined
        //      one iteration ahead); w loads are warp-uniform broadcasts.
        {
            uint64_t acc0 = 0, acc1 = 0, acc2 = 0, acc3 = 0;  // node pairs (0,1)(2,3)(4,5)(6,7)
            const float* wp = wS + ng * 8;
            float4 g4 = *reinterpret_cast<const float4*>(grow);        // prefetch k4=0
            #pragma unroll 4
            for (int k4 = 0; k4 < 512; k4 += 4) {
                float4 gcur = g4;
                if (k4 + 4 < 512)
                    g4 = *reinterpret_cast<const float4*>(grow + k4 + 4);  // prefetch next
                const float* gv = reinterpret_cast<const float*>(&gcur);
                #pragma unroll
                for (int u = 0; u < 4; ++u) {
                    uint32_t gu = __float_as_uint(gv[u]);
                    uint64_t gg;
                    asm("mov.b64 %0, {%1, %1};" : "=l"(gg) : "r"(gu));
                    ulonglong2 wA = *reinterpret_cast<const ulonglong2*>(wp + (k4 + u) * 32);
                    ulonglong2 wB = *reinterpret_cast<const ulonglong2*>(wp + (k4 + u) * 32 + 4);
                    FMA_F32X2(acc0, gg, wA.x);
                    FMA_F32X2(acc1, gg, wA.y);
                    FMA_F32X2(acc2, gg, wB.x);
                    FMA_F32X2(acc3, gg, wB.y);
                }
            }
            // unpack: node m gets T[base+m][j]
            float tv[8];
            tv[0] = __uint_as_float((uint32_t)acc0);  tv[1] = __uint_as_float((uint32_t)(acc0 >> 32));
            tv[2] = __uint_as_float((uint32_t)acc1);  tv[3] = __uint_as_float((uint32_t)(acc1 >> 32));
            tv[4] = __uint_as_float((uint32_t)acc2);  tv[5] = __uint_as_float((uint32_t)(acc2 >> 32));
            tv[6] = __uint_as_float((uint32_t)acc3);  tv[7] = __uint_as_float((uint32_t)(acc3 >> 32));
            #pragma unroll
            for (int m = 0; m < 8; ++m)
                Ts[(ng * 8 + m) * 64 + j] = tv[m];
        }
        __syncthreads();

        // fold with ris0: thread -> (nl = t>>3, a1 = t&7)
        {
            const int nl = t >> 3, a1 = t & 7;
            float s = 0.f;
            #pragma unroll
            for (int a0 = 0; a0 < 8; ++a0)
                s = fmaf(Ts[nl * 64 + a0 * 8 + a1], rT[a0 * 33 + nl], s);
            ss[nl * 9 + a1] = s;
        }
        __syncthreads();

        // output GEMM: thread -> (nl = t>>3, oh = t&7), 16 outputs each
        {
            const int nl = t >> 3, oh = t & 7;
            const int node = base + nl;
            if (node < n) {
                float4 o0 = make_float4(0.f,0.f,0.f,0.f), o1 = o0, o2 = o0, o3 = o0;
                #pragma unroll
                for (int a1 = 0; a1 < 8; ++a1) {
                    float sv = ss[nl * 9 + a1];
                    const float4* up = reinterpret_cast<const float4*>(Uos + a1 * 128 + oh * 16);
                    float4 u0 = up[0], u1 = up[1], u2 = up[2], u3 = up[3];
                    o0.x = fmaf(sv, u0.x, o0.x); o0.y = fmaf(sv, u0.y, o0.y);
                    o0.z = fmaf(sv, u0.z, o0.z); o0.w = fmaf(sv, u0.w, o0.w);
                    o1.x = fmaf(sv, u1.x, o1.x); o1.y = fmaf(sv, u1.y, o1.y);
                    o1.z = fmaf(sv, u1.z, o1.z); o1.w = fmaf(sv, u1.w, o1.w);
                    o2.x = fmaf(sv, u2.x, o2.x); o2.y = fmaf(sv, u2.y, o2.y);
                    o2.z = fmaf(sv, u2.z, o2.z); o2.w = fmaf(sv, u2.w, o2.w);
                    o3.x = fmaf(sv, u3.x, o3.x); o3.y = fmaf(sv, u3.y, o3.y);
                    o3.z = fmaf(sv, u3.z, o3.z); o3.w = fmaf(sv, u3.w, o3.w);
                }
                float4* og = reinterpret_cast<float4*>(out + (size_t)node * 128 + oh * 16);
                og[0] = o0; og[1] = o1; og[2] = o2; og[3] = o3;
            }
        }
        __syncthreads();   // before next tile reuses rT / wS / Ts / ss
    }
}

// ---------------- launch ----------------
extern "C" void kernel_launch(void* const* d_in, const int* in_sizes, int n_in,
                              void* d_out, int out_size)
{
    const float* x  = (const float*)d_in[0];   // [N,4,256]
    const float* G  = (const float*)d_in[1];   // [8,8,8,8,8]
    const float* Us = (const float*)d_in[2];   // [4,256,8]
    const float* Uo = (const float*)d_in[3];   // [8,128]
    float* out = (float*)d_out;                // [N,128]

    int n = in_sizes[0] / 1024;
    if (n < 0) n = 0;
    if (n > MAX_N) n = MAX_N;                  // scratch safety (dataset N=50000)
    int ntiles = (n + TILE - 1) / TILE;
    if (ntiles == 0) return;

    cudaFuncSetAttribute(ris_kernel,  cudaFuncAttributeMaxDynamicSharedMemorySize,
                         K1_SMEM_FLOATS * 4);
    cudaFuncSetAttribute(core_kernel, cudaFuncAttributeMaxDynamicSharedMemorySize,
                         K2_SMEM_FLOATS * 4);

    int nsm = 148;
    cudaDeviceGetAttribute(&nsm, cudaDevAttrMultiProcessorCount, 0);
    int grid2 = (nsm < ntiles) ? nsm : ntiles;

    ris_kernel<<<ntiles, THREADS, K1_SMEM_FLOATS * 4>>>(x, Us, n);
    core_kernel<<<grid2, THREADS, K2_SMEM_FLOATS * 4>>>(G, Uo, out, n, ntiles);
}

// round 8
// speedup vs baseline: 1.0042x; 1.0042x over previous
#include <cuda_runtime.h>
#include <cstdint>

// HOSVD aggregator:
//   ris[n,d,r] = sum_i x[n,d,i]*U_stack[d,i,r]            (kernel 1)
//   w[n,k]     = ris3[a2]*ris2[a3]*ris1[a4]               (kernel 2, chunked by a2)
//   T[n,j]     = sum_k w[n,k]*G[j,k]   (j=a0*8+a1)        (kernel 2, 8jx8n reg tiles, f32x2)
//   s[n,a1]    = sum_a0 T[n,a0*8+a1]*ris0[a0]             (kernel 2)
//   out[n,o]   = sum_a1 s[n,a1]*U_output[a1,o]            (kernel 2)

#define MAX_N    50016

__device__ float g_ris[MAX_N * 32];

#define FMA_F32X2(acc, a, b) \
    asm("fma.rn.f32x2 %0, %1, %2, %0;" : "+l"(acc) : "l"(a), "l"(b))

// ---------------- kernel 1: ris projection ----------------
// 16 nodes/tile, 256 threads: (nl = t>>4, r = (t>>1)&7, half = t&1).
// smem 98.8KB -> 2 CTAs/SM (16 warps).
#define K1_TILE 16
#define K1_THREADS 256
#define K1_XS  0                          // 16*1024 floats
#define K1_UST 16384                      // 32 rows * 260
#define K1_SMEM_FLOATS (16384 + 32 * 260) // 24704 floats = 98816 B

__global__ void __launch_bounds__(K1_THREADS, 2)
ris_kernel(const float* __restrict__ x, const float* __restrict__ Ustack, int n)
{
    extern __shared__ float sm1[];
    float* Xs  = sm1 + K1_XS;
    float* UsT = sm1 + K1_UST;
    const int t = threadIdx.x;

    // stage U_stack transposed: UsT[(d*8+r)*260 + i] = U_stack[d][i][r]
    for (int idx = t; idx < 8192; idx += K1_THREADS) {
        int d = idx >> 11;
        int i = (idx >> 3) & 255;
        int r = idx & 7;
        UsT[(d * 8 + r) * 260 + i] = Ustack[idx];
    }

    const int base = blockIdx.x * K1_TILE;
    const float4* xg = reinterpret_cast<const float4*>(x) + (size_t)base * 256;
    float4* Xs4 = reinterpret_cast<float4*>(Xs);
    if (base + K1_TILE <= n) {
        for (int idx = t; idx < 4096; idx += K1_THREADS) Xs4[idx] = xg[idx];
    } else {
        for (int idx = t; idx < 4096; idx += K1_THREADS) {
            int node = base + (idx >> 8);
            Xs4[idx] = (node < n) ? xg[idx] : make_float4(0.f, 0.f, 0.f, 0.f);
        }
    }
    __syncthreads();

    const int nl   = t >> 4;
    const int r    = (t >> 1) & 7;
    const int half = t & 1;
    const int node = base + nl;
    #pragma unroll
    for (int d = 0; d < 4; ++d) {
        const float* xr = Xs + nl * 1024 + d * 256 + half * 128;
        const float* ur = UsT + (d * 8 + r) * 260 + half * 128;
        float a0 = 0.f, a1 = 0.f, a2 = 0.f, a3 = 0.f;
        #pragma unroll 8
        for (int i = 0; i < 128; i += 4) {
            float4 xv = *reinterpret_cast<const float4*>(xr + i);
            float4 uv = *reinterpret_cast<const float4*>(ur + i);
            a0 = fmaf(xv.x, uv.x, a0);
            a1 = fmaf(xv.y, uv.y, a1);
            a2 = fmaf(xv.z, uv.z, a2);
            a3 = fmaf(xv.w, uv.w, a3);
        }
        float s = (a0 + a1) + (a2 + a3);
        s += __shfl_xor_sync(0xffffffffu, s, 1);
        if (!half && node < n) g_ris[node * 32 + d * 8 + r] = s;
    }
}

// ---------------- kernel 2: core, warp-private 8jx8n register tiles ----------------
// Gs[k][j] stride 68 (16B-aligned rows). Per warp: private wS region (2112 floats)
// used as w[64][32] during GEMM chunks and as T[32][66] for the epilogue.
#define THREADS2 256
#define NWARPS   8
#define GST      68
#define GS_OFF   0                         // 512*68 = 34816 floats
#define WS_OFF   34816                     // + warp*2112
#define WS_PER   2112                      // max(64*32, 32*66)
#define UO_OFF   (34816 + NWARPS * WS_PER) // 51712
#define K2_SMEM_FLOATS (UO_OFF + 1024)     // 52736 floats = 210944 B

__global__ void __launch_bounds__(THREADS2, 1)
core_kernel(const float* __restrict__ G, const float* __restrict__ Uout,
            float* __restrict__ out, int n, int ntiles)
{
    extern __shared__ float sm2[];
    float* Gs  = sm2 + GS_OFF;
    float* Uos = sm2 + UO_OFF;

    const int t = threadIdx.x;
    const int warp = t >> 5, lane = t & 31;
    float* wSw = sm2 + WS_OFF + warp * WS_PER;

    // stage G (gmem layout is [j][k], j=a0*8+a1, k=a2*64+a3*8+a4) into Gs[k*68+j].
    // Reads coalesced; STS conflicts only in this one-time loop.
    for (int idx = t; idx < 32768; idx += THREADS2) {
        int j = idx >> 9;
        int k = idx & 511;
        Gs[k * GST + j] = G[idx];
    }
    for (int idx = t; idx < 1024; idx += THREADS2) Uos[idx] = Uout[idx];
    __syncthreads();

    const int jg = lane & 7;    // j-group: 8 j's at jg*8
    const int ng = lane >> 3;   // n-group: 8 nodes at ng*8

    for (int tile = blockIdx.x * NWARPS + warp; tile < ntiles;
         tile += gridDim.x * NWARPS) {
        const int base = tile * 32;
        const int node = base + lane;

        // per-lane ris factors for node = base+lane
        float r0[8], r1[8], r2[8], r3[8];
        if (node < n) {
            const float4* rp = reinterpret_cast<const float4*>(g_ris + (size_t)node * 32);
            float4 v;
            v = rp[0]; r0[0]=v.x; r0[1]=v.y; r0[2]=v.z; r0[3]=v.w;
            v = rp[1]; r0[4]=v.x; r0[5]=v.y; r0[6]=v.z; r0[7]=v.w;
            v = rp[2]; r1[0]=v.x; r1[1]=v.y; r1[2]=v.z; r1[3]=v.w;
            v = rp[3]; r1[4]=v.x; r1[5]=v.y; r1[6]=v.z; r1[7]=v.w;
            v = rp[4]; r2[0]=v.x; r2[1]=v.y; r2[2]=v.z; r2[3]=v.w;
            v = rp[5]; r2[4]=v.x; r2[5]=v.y; r2[6]=v.z; r2[7]=v.w;
            v = rp[6]; r3[0]=v.x; r3[1]=v.y; r3[2]=v.z; r3[3]=v.w;
            v = rp[7]; r3[4]=v.x; r3[5]=v.y; r3[6]=v.z; r3[7]=v.w;
        } else {
            #pragma unroll
            for (int i = 0; i < 8; ++i) { r0[i]=0.f; r1[i]=0.f; r2[i]=0.f; r3[i]=0.f; }
        }

        uint64_t acc[8][4];   // [ji][n-pair]: 8 j x 8 n
        #pragma unroll
        for (int a = 0; a < 8; ++a)
            #pragma unroll
            for (int b = 0; b < 4; ++b) acc[a][b] = 0;

        #pragma unroll 1
        for (int c = 0; c < 8; ++c) {
            // ---- build w chunk (a2 = c): w[a3*8+a4][lane] ----
            __syncwarp();
            #pragma unroll
            for (int a3 = 0; a3 < 8; ++a3) {
                float p = r3[c] * r2[a3];
                #pragma unroll
                for (int a4 = 0; a4 < 8; ++a4)
                    wSw[(a3 * 8 + a4) * 32 + lane] = p * r1[a4];
            }
            __syncwarp();

            // ---- GEMM over this 64-k chunk ----
            const float* gp = Gs + (c * 64) * GST + jg * 8;
            const float* wp = wSw + ng * 8;
            float4 g0 = *reinterpret_cast<const float4*>(gp);
            float4 g1 = *reinterpret_cast<const float4*>(gp + 4);
            ulonglong2 w0 = *reinterpret_cast<const ulonglong2*>(wp);
            ulonglong2 w1 = *reinterpret_cast<const ulonglong2*>(wp + 4);
            #pragma unroll 4
            for (int kc = 0; kc < 64; ++kc) {
                float4 cg0 = g0, cg1 = g1;
                ulonglong2 cw0 = w0, cw1 = w1;
                if (kc + 1 < 64) {
                    g0 = *reinterpret_cast<const float4*>(gp + (kc + 1) * GST);
                    g1 = *reinterpret_cast<const float4*>(gp + (kc + 1) * GST + 4);
                    w0 = *reinterpret_cast<const ulonglong2*>(wp + (kc + 1) * 32);
                    w1 = *reinterpret_cast<const ulonglong2*>(wp + (kc + 1) * 32 + 4);
                }
                const float* gv0 = reinterpret_cast<const float*>(&cg0);
                const float* gv1 = reinterpret_cast<const float*>(&cg1);
                uint64_t gg;
                #pragma unroll
                for (int ji = 0; ji < 4; ++ji) {
                    asm("mov.b64 %0, {%1, %1};" : "=l"(gg) : "r"(__float_as_uint(gv0[ji])));
                    FMA_F32X2(acc[ji][0], gg, cw0.x);
                    FMA_F32X2(acc[ji][1], gg, cw0.y);
                    FMA_F32X2(acc[ji][2], gg, cw1.x);
                    FMA_F32X2(acc[ji][3], gg, cw1.y);
                }
                #pragma unroll
                for (int ji = 0; ji < 4; ++ji) {
                    asm("mov.b64 %0, {%1, %1};" : "=l"(gg) : "r"(__float_as_uint(gv1[ji])));
                    FMA_F32X2(acc[4 + ji][0], gg, cw0.x);
                    FMA_F32X2(acc[4 + ji][1], gg, cw0.y);
                    FMA_F32X2(acc[4 + ji][2], gg, cw1.x);
                    FMA_F32X2(acc[4 + ji][3], gg, cw1.y);
                }
            }
        }

        // ---- write T[n_local][j] into wSw (stride 66) ----
        __syncwarp();
        #pragma unroll
        for (int ji = 0; ji < 8; ++ji) {
            #pragma unroll
            for (int np = 0; np < 4; ++np) {
                uint64_t a = acc[ji][np];
                wSw[(ng * 8 + 2 * np    ) * 66 + jg * 8 + ji] =
                    __uint_as_float((uint32_t)a);
                wSw[(ng * 8 + 2 * np + 1) * 66 + jg * 8 + ji] =
                    __uint_as_float((uint32_t)(a >> 32));
            }
        }
        __syncwarp();

        // ---- epilogue per lane (node = base+lane) ----
        if (node < n) {
            const float* Trow = wSw + lane * 66;
            float s[8];
            #pragma unroll
            for (int a1 = 0; a1 < 8; ++a1) {
                float sv = 0.f;
                #pragma unroll
                for (int a0 = 0; a0 < 8; ++a0)
                    sv = fmaf(Trow[a0 * 8 + a1], r0[a0], sv);
                s[a1] = sv;
            }
            float* orow = out + (size_t)node * 128;
            #pragma unroll 4
            for (int o = 0; o < 128; o += 4) {
                float4 ov = make_float4(0.f, 0.f, 0.f, 0.f);
                #pragma unroll
                for (int a1 = 0; a1 < 8; ++a1) {
                    float sv = s[a1];
                    float4 uv = *reinterpret_cast<const float4*>(Uos + a1 * 128 + o);
                    ov.x = fmaf(sv, uv.x, ov.x);
                    ov.y = fmaf(sv, uv.y, ov.y);
                    ov.z = fmaf(sv, uv.z, ov.z);
                    ov.w = fmaf(sv, uv.w, ov.w);
                }
                *reinterpret_cast<float4*>(orow + o) = ov;
            }
        }
        // next iteration's build starts with __syncwarp(), protecting wSw reuse
    }
}

// ---------------- launch ----------------
extern "C" void kernel_launch(void* const* d_in, const int* in_sizes, int n_in,
                              void* d_out, int out_size)
{
    const float* x  = (const float*)d_in[0];   // [N,4,256]
    const float* G  = (const float*)d_in[1];   // [8,8,8,8,8]
    const float* Us = (const float*)d_in[2];   // [4,256,8]
    const float* Uo = (const float*)d_in[3];   // [8,128]
    float* out = (float*)d_out;                // [N,128]

    int n = in_sizes[0] / 1024;
    if (n < 0) n = 0;
    if (n > MAX_N) n = MAX_N;
    int ntiles1 = (n + K1_TILE - 1) / K1_TILE;
    int ntiles2 = (n + 31) / 32;
    if (ntiles2 == 0) return;

    cudaFuncSetAttribute(ris_kernel,  cudaFuncAttributeMaxDynamicSharedMemorySize,
                         K1_SMEM_FLOATS * 4);
    cudaFuncSetAttribute(core_kernel, cudaFuncAttributeMaxDynamicSharedMemorySize,
                         K2_SMEM_FLOATS * 4);

    int nsm = 148;
    cudaDeviceGetAttribute(&nsm, cudaDevAttrMultiProcessorCount, 0);
    int needed = (ntiles2 + NWARPS - 1) / NWARPS;
    int grid2 = (nsm < needed) ? nsm : needed;

    ris_kernel<<<ntiles1, K1_THREADS, K1_SMEM_FLOATS * 4>>>(x, Us, n);
    core_kernel<<<grid2, THREADS2, K2_SMEM_FLOATS * 4>>>(G, Uo, out, n, ntiles2);
}

// round 9
// speedup vs baseline: 1.6597x; 1.6528x over previous
#include <cuda_runtime.h>
#include <cstdint>

// HOSVD aggregator:
//   ris[n,d,r] = sum_i x[n,d,i]*U_stack[d,i,r]         (kernel 1, thread=node, U broadcast)
//   w[n,k]     = ris3[a2]*ris2[a3]*ris1[a4]            (kernel 2, per-warp chunks by a2)
//   T[n,j]     = sum_k w[n,k]*G[j,k]  (j=a0*8+a1)      (kernel 2, 8j x 4n reg tiles, f32x2 j-pairs)
//   s[n,a1]    = sum_a0 T[n,a0*8+a1]*ris0[a0]          (kernel 2)
//   out[n,o]   = sum_a1 s[n,a1]*U_output[a1,o]         (kernel 2)

#define MAX_N 50016

// g_ris TRANSPOSED: g_ris[dr * MAX_N + node]  (coalesced writes in k1, coalesced reads in k2)
__device__ float g_ris[32 * MAX_N];

#define FMA_F32X2(acc, a, b) \
    asm("fma.rn.f32x2 %0, %1, %2, %0;" : "+l"(acc) : "l"(a), "l"(b))
#define DUP_F32(dst64, src32) \
    asm("mov.b64 %0, {%1, %1};" : "=l"(dst64) : "r"(src32))

// ---------------- kernel 1: ris projection (thread = node) ----------------
// smem: Us[8192] (raw [d][i][r]), Xs[64][257] transposed x chunk.
// 98.6 KB -> 2 CTAs/SM. Per i: 1 LDS x (conflict-free), 2 broadcast LDS u, 4 FFMA2.
#define R_THREADS 256
#define R_TILE    256
#define R_XS_OFF  8192
#define R_SMEM_FLOATS (8192 + 64 * 257)   // 24640 floats = 98560 B

__global__ void __launch_bounds__(R_THREADS, 2)
ris_kernel(const float* __restrict__ x, const float* __restrict__ Ustack, int n)
{
    extern __shared__ float sm1[];
    float* Us = sm1;
    float* Xs = sm1 + R_XS_OFF;
    const int t = threadIdx.x;

    for (int idx = t; idx < 8192; idx += R_THREADS) Us[idx] = Ustack[idx];

    const int base = blockIdx.x * R_TILE;
    const int node = base + t;
    const float4* xg4 = reinterpret_cast<const float4*>(x);

    #pragma unroll 1
    for (int d = 0; d < 4; ++d) {
        uint64_t acc[4] = {0, 0, 0, 0};   // r-pairs (0,1)(2,3)(4,5)(6,7)
        #pragma unroll 1
        for (int ic = 0; ic < 4; ++ic) {
            __syncthreads();   // protect Xs reuse (also orders Us staging on first pass)
            // stage x chunk transposed: Xs[i_local][node_local], i_local = f4*4+q
            #pragma unroll 4
            for (int idx = t; idx < 4096; idx += R_THREADS) {
                int nl = idx >> 4, f4 = idx & 15;
                float4 v = make_float4(0.f, 0.f, 0.f, 0.f);
                if (base + nl < n)
                    v = xg4[(size_t)(base + nl) * 256 + d * 64 + ic * 16 + f4];
                int ib = f4 * 4;
                Xs[(ib + 0) * 257 + nl] = v.x;
                Xs[(ib + 1) * 257 + nl] = v.y;
                Xs[(ib + 2) * 257 + nl] = v.z;
                Xs[(ib + 3) * 257 + nl] = v.w;
            }
            __syncthreads();

            const float* up = Us + d * 2048 + ic * 512;   // U[d][ic*64 + i][0..7]
            #pragma unroll 8
            for (int i = 0; i < 64; ++i) {
                float xv = Xs[i * 257 + t];
                uint64_t xx; DUP_F32(xx, __float_as_uint(xv));
                ulonglong2 u0 = *reinterpret_cast<const ulonglong2*>(up + i * 8);
                ulonglong2 u1 = *reinterpret_cast<const ulonglong2*>(up + i * 8 + 4);
                FMA_F32X2(acc[0], xx, u0.x);
                FMA_F32X2(acc[1], xx, u0.y);
                FMA_F32X2(acc[2], xx, u1.x);
                FMA_F32X2(acc[3], xx, u1.y);
            }
        }
        if (node < n) {
            #pragma unroll
            for (int p = 0; p < 4; ++p) {
                g_ris[(d * 8 + 2 * p    ) * MAX_N + node] =
                    __uint_as_float((uint32_t)acc[p]);
                g_ris[(d * 8 + 2 * p + 1) * MAX_N + node] =
                    __uint_as_float((uint32_t)(acc[p] >> 32));
            }
        }
    }
}

// ---------------- kernel 2: core, 16 warps x 16-node warp tiles ----------------
// Gs[k][j] stride 68. Per-warp region: w[64][16] (1024) / T[16][66] (1056).
// Lane = (jg = lane>>2: 8 j's at jg*8 as 4 f32x2 j-pairs) x (ng = lane&3: 4 nodes).
#define C_THREADS 512
#define C_NW      16
#define GST       68
#define C_GS_OFF  0                            // 512*68 = 34816
#define C_WS_OFF  34816
#define C_WS_PER  1056
#define C_UO_OFF  (34816 + C_NW * C_WS_PER)    // 51712
#define C_SMEM_FLOATS (C_UO_OFF + 1024)        // 52736 floats = 210944 B

__global__ void __launch_bounds__(C_THREADS, 1)
core_kernel(const float* __restrict__ G, const float* __restrict__ Uout,
            float* __restrict__ out, int n, int ntiles)
{
    extern __shared__ float sm2[];
    float* Gs  = sm2 + C_GS_OFF;
    float* Uos = sm2 + C_UO_OFF;

    const int t = threadIdx.x;
    const int warp = t >> 5, lane = t & 31;
    float* wSw = sm2 + C_WS_OFF + warp * C_WS_PER;

    // stage G ([j][k] in gmem) into Gs[k*68 + j]; copy U_output
    for (int idx = t; idx < 32768; idx += C_THREADS) {
        int j = idx >> 9;
        int k = idx & 511;
        Gs[k * GST + j] = G[idx];
    }
    for (int idx = t; idx < 1024; idx += C_THREADS) Uos[idx] = Uout[idx];
    __syncthreads();

    const int jg = lane >> 2;    // 0..7
    const int ng = lane & 3;     // 0..3
    const int nl = lane & 15;    // node-local for build/epilogue
    const int h  = lane >> 4;    // half for build/epilogue

    for (int tile = blockIdx.x * C_NW + warp; tile < ntiles;
         tile += gridDim.x * C_NW) {
        const int base = tile * 16;
        const int mynode = base + nl;

        // per-lane ris factors (rows of transposed g_ris; coalesced LDG)
        float r0[8], r1[8], r2[8], r3[8];
        #pragma unroll
        for (int a = 0; a < 8; ++a) {
            r0[a] = g_ris[(     a) * MAX_N + mynode];
            r1[a] = g_ris[( 8 + a) * MAX_N + mynode];
            r2[a] = g_ris[(16 + a) * MAX_N + mynode];
            r3[a] = g_ris[(24 + a) * MAX_N + mynode];
        }

        uint64_t acc[4][4];   // [j-pair][node]: j = jg*8 + 2*jp (+1), node = ng*4+nn
        #pragma unroll
        for (int a = 0; a < 4; ++a)
            #pragma unroll
            for (int b = 0; b < 4; ++b) acc[a][b] = 0;

        #pragma unroll 1
        for (int c = 0; c < 8; ++c) {
            // ---- build w chunk (a2 = c): w[(a3*8+a4)*16 + nl] ----
            __syncwarp();
            #pragma unroll
            for (int a3o = 0; a3o < 4; ++a3o) {
                int a3 = h * 4 + a3o;
                float p = r3[c] * r2[a3];
                #pragma unroll
                for (int a4 = 0; a4 < 8; ++a4)
                    wSw[(a3 * 8 + a4) * 16 + nl] = p * r1[a4];
            }
            __syncwarp();

            // ---- GEMM over 64-k chunk; j-pairs come straight from g loads ----
            const float* gp = Gs + (c * 64) * GST + jg * 8;
            const float* wp = wSw + ng * 4;
            ulonglong2 ga = *reinterpret_cast<const ulonglong2*>(gp);
            ulonglong2 gb = *reinterpret_cast<const ulonglong2*>(gp + 4);
            float4     wv = *reinterpret_cast<const float4*>(wp);
            #pragma unroll 4
            for (int kc = 0; kc < 64; ++kc) {
                ulonglong2 cga = ga, cgb = gb;
                float4 cwv = wv;
                if (kc + 1 < 64) {
                    ga = *reinterpret_cast<const ulonglong2*>(gp + (kc + 1) * GST);
                    gb = *reinterpret_cast<const ulonglong2*>(gp + (kc + 1) * GST + 4);
                    wv = *reinterpret_cast<const float4*>(wp + (kc + 1) * 16);
                }
                uint64_t w0, w1, w2, w3;
                DUP_F32(w0, __float_as_uint(cwv.x));
                DUP_F32(w1, __float_as_uint(cwv.y));
                DUP_F32(w2, __float_as_uint(cwv.z));
                DUP_F32(w3, __float_as_uint(cwv.w));
                FMA_F32X2(acc[0][0], cga.x, w0); FMA_F32X2(acc[0][1], cga.x, w1);
                FMA_F32X2(acc[0][2], cga.x, w2); FMA_F32X2(acc[0][3], cga.x, w3);
                FMA_F32X2(acc[1][0], cga.y, w0); FMA_F32X2(acc[1][1], cga.y, w1);
                FMA_F32X2(acc[1][2], cga.y, w2); FMA_F32X2(acc[1][3], cga.y, w3);
                FMA_F32X2(acc[2][0], cgb.x, w0); FMA_F32X2(acc[2][1], cgb.x, w1);
                FMA_F32X2(acc[2][2], cgb.x, w2); FMA_F32X2(acc[2][3], cgb.x, w3);
                FMA_F32X2(acc[3][0], cgb.y, w0); FMA_F32X2(acc[3][1], cgb.y, w1);
                FMA_F32X2(acc[3][2], cgb.y, w2); FMA_F32X2(acc[3][3], cgb.y, w3);
            }
        }

        // ---- write T[n_local][j] into wSw (stride 66) ----
        __syncwarp();
        #pragma unroll
        for (int jp = 0; jp < 4; ++jp) {
            int j0 = jg * 8 + 2 * jp;
            #pragma unroll
            for (int nn = 0; nn < 4; ++nn) {
                uint64_t a = acc[jp][nn];
                float* Tp = wSw + (ng * 4 + nn) * 66 + j0;
                Tp[0] = __uint_as_float((uint32_t)a);
                Tp[1] = __uint_as_float((uint32_t)(a >> 32));
            }
        }
        __syncwarp();

        // ---- epilogue: lane handles node = base+nl, output half h ----
        if (mynode < n) {
            const float* Trow = wSw + nl * 66;
            float s[8];
            #pragma unroll
            for (int a1 = 0; a1 < 8; ++a1) {
                float sv = 0.f;
                #pragma unroll
                for (int a0 = 0; a0 < 8; ++a0)
                    sv = fmaf(Trow[a0 * 8 + a1], r0[a0], sv);
                s[a1] = sv;
            }
            float* orow = out + (size_t)mynode * 128 + h * 64;
            const float* ub = Uos + h * 64;
            #pragma unroll 4
            for (int o = 0; o < 64; o += 4) {
                float4 ov = make_float4(0.f, 0.f, 0.f, 0.f);
                #pragma unroll
                for (int a1 = 0; a1 < 8; ++a1) {
                    float sv = s[a1];
                    float4 uv = *reinterpret_cast<const float4*>(ub + a1 * 128 + o);
                    ov.x = fmaf(sv, uv.x, ov.x);
                    ov.y = fmaf(sv, uv.y, ov.y);
                    ov.z = fmaf(sv, uv.z, ov.z);
                    ov.w = fmaf(sv, uv.w, ov.w);
                }
                *reinterpret_cast<float4*>(orow + o) = ov;
            }
        }
        // next tile's build starts with __syncwarp(), protecting wSw reuse
    }
}

// ---------------- launch ----------------
extern "C" void kernel_launch(void* const* d_in, const int* in_sizes, int n_in,
                              void* d_out, int out_size)
{
    const float* x  = (const float*)d_in[0];   // [N,4,256]
    const float* G  = (const float*)d_in[1];   // [8,8,8,8,8]
    const float* Us = (const float*)d_in[2];   // [4,256,8]
    const float* Uo = (const float*)d_in[3];   // [8,128]
    float* out = (float*)d_out;                // [N,128]

    int n = in_sizes[0] / 1024;
    if (n < 0) n = 0;
    if (n > MAX_N) n = MAX_N;
    int nblk1  = (n + R_TILE - 1) / R_TILE;
    int ntiles = (n + 15) / 16;
    if (ntiles == 0) return;

    cudaFuncSetAttribute(ris_kernel,  cudaFuncAttributeMaxDynamicSharedMemorySize,
                         R_SMEM_FLOATS * 4);
    cudaFuncSetAttribute(core_kernel, cudaFuncAttributeMaxDynamicSharedMemorySize,
                         C_SMEM_FLOATS * 4);

    int nsm = 148;
    cudaDeviceGetAttribute(&nsm, cudaDevAttrMultiProcessorCount, 0);
    int needed = (ntiles + C_NW - 1) / C_NW;
    int grid2 = (nsm < needed) ? nsm : needed;

    ris_kernel<<<nblk1, R_THREADS, R_SMEM_FLOATS * 4>>>(x, Us, n);
    core_kernel<<<grid2, C_THREADS, C_SMEM_FLOATS * 4>>>(G, Uo, out, n, ntiles);
}

// round 16
// speedup vs baseline: 2.0060x; 1.2086x over previous
#include <cuda_runtime.h>
#include <cstdint>

// HOSVD aggregator:
//   ris[n,d,r] = sum_i x[n,d,i]*U_stack[d,i,r]      (kernel 1, cp.async pipelined)
//   w[n,k]     = ris3[a2]*ris2[a3]*ris1[a4]         (kernel 2, per-warp f32x2 build)
//   T[n,j]     = sum_k w[n,k]*G[j,k]  (j=a0*8+a1)   (kernel 2, 8j x 2n f32x2 reg tiles)
//   s[n,a1]    = sum_a0 T[n,a0*8+a1]*ris0[a0]       (kernel 2)
//   out[n,o]   = sum_a1 s[n,a1]*U_output[a1,o]      (kernel 2)

#define MAX_N 50016

// g_ris transposed: g_ris[dr * MAX_N + node]
__device__ float g_ris[32 * MAX_N];

#define FMA_F32X2(acc, a, b) \
    asm("fma.rn.f32x2 %0, %1, %2, %0;" : "+l"(acc) : "l"(a), "l"(b))
#define MUL_F32X2(o, a, b) \
    asm("mul.rn.f32x2 %0, %1, %2;" : "=l"(o) : "l"(a), "l"(b))
#define DUP_F32(dst64, src32) \
    asm("mov.b64 %0, {%1, %1};" : "=l"(dst64) : "r"(src32))

// ================= kernel 1: ris projection =================
// 128 nodes/CTA, 32-i chunks double-buffered via cp.async. 3 CTAs/SM.
#define R_THREADS 128
#define R_TILE    128
#define R_P       36                        // Xs row stride (floats), 16B-aligned
#define R_BUF     (128 * R_P)               // 4608 floats per buffer
#define R_SMEM_FLOATS (8192 + 2 * R_BUF)    // 17408 floats = 69632 B

__device__ __forceinline__ void ris_stage(const float4* xg4, float* Xb,
                                          int base, int cg, int n, int t)
{
    #pragma unroll
    for (int it = 0; it < 8; ++it) {
        int idx = t + it * R_THREADS;       // 0..1023
        int nl = idx >> 3, f4 = idx & 7;
        int gn = base + nl;
        int ok = gn < n;
        const float4* src = xg4 + (size_t)(ok ? gn : 0) * 256 + cg * 8 + f4;
        int sz = ok ? 16 : 0;
        uint32_t dst = (uint32_t)__cvta_generic_to_shared(Xb + nl * R_P + f4 * 4);
        asm volatile("cp.async.cg.shared.global [%0], [%1], 16, %2;"
                     :: "r"(dst), "l"(src), "r"(sz));
    }
    asm volatile("cp.async.commit_group;");
}

__device__ __forceinline__ void ris_compute(const float* Us, const float* Xb,
                                            int cg, int t, uint64_t acc[4])
{
    const float* up = Us + (cg >> 3) * 2048 + (cg & 7) * 256;
    const float* xr = Xb + t * R_P;
    #pragma unroll 2
    for (int iq = 0; iq < 8; ++iq) {
        float4 xv = *reinterpret_cast<const float4*>(xr + iq * 4);
        const float* xs = reinterpret_cast<const float*>(&xv);
        #pragma unroll
        for (int q = 0; q < 4; ++q) {
            uint64_t xx; DUP_F32(xx, __float_as_uint(xs[q]));
            ulonglong2 u0 = *reinterpret_cast<const ulonglong2*>(up + (iq * 4 + q) * 8);
            ulonglong2 u1 = *reinterpret_cast<const ulonglong2*>(up + (iq * 4 + q) * 8 + 4);
            FMA_F32X2(acc[0], xx, u0.x);
            FMA_F32X2(acc[1], xx, u0.y);
            FMA_F32X2(acc[2], xx, u1.x);
            FMA_F32X2(acc[3], xx, u1.y);
        }
    }
}

__global__ void __launch_bounds__(R_THREADS, 3)
ris_kernel(const float* __restrict__ x, const float* __restrict__ Ustack, int n)
{
    extern __shared__ float sm1[];
    float* Us = sm1;
    float* X0 = sm1 + 8192;
    float* X1 = X0 + R_BUF;
    const int t = threadIdx.x;

    for (int idx = t; idx < 8192; idx += R_THREADS) Us[idx] = Ustack[idx];

    const int base = blockIdx.x * R_TILE;
    const int node = base + t;
    const float4* xg4 = reinterpret_cast<const float4*>(x);

    uint64_t acc[4] = {0, 0, 0, 0};
    ris_stage(xg4, X0, base, 0, n, t);

    #pragma unroll 1
    for (int cg = 0; cg < 32; ++cg) {
        float* cur = (cg & 1) ? X1 : X0;
        if (cg < 31) {
            ris_stage(xg4, (cg & 1) ? X0 : X1, base, cg + 1, n, t);
            asm volatile("cp.async.wait_group 1;");
        } else {
            asm volatile("cp.async.wait_group 0;");
        }
        __syncthreads();
        ris_compute(Us, cur, cg, t, acc);
        if ((cg & 7) == 7) {
            if (node < n) {
                int d = cg >> 3;
                #pragma unroll
                for (int p = 0; p < 4; ++p) {
                    g_ris[(d * 8 + 2 * p    ) * MAX_N + node] =
                        __uint_as_float((uint32_t)acc[p]);
                    g_ris[(d * 8 + 2 * p + 1) * MAX_N + node] =
                        __uint_as_float((uint32_t)(acc[p] >> 32));
                }
            }
            acc[0] = acc[1] = acc[2] = acc[3] = 0;
        }
        __syncthreads();   // protect buffer consumed this iter before re-staging
    }
}

// ================= kernel 2: core, 8-node warp tiles =================
// GsA[k][32] holds G[jg*8+m][k] (m 0..3), GsB the m 4..7 half -> conflict-free LDS.128.
// Per-warp: wSw (w[64][10] / T[8][66]) + rSw[24][8].
#define C_THREADS 512
#define C_NW      16
#define C_GSA 0
#define C_GSB 16384
#define C_W   32768
#define C_WPER 832                            // 640 (w/T) + 192 (rS)
#define C_UO  (C_W + C_NW * C_WPER)           // 46080
#define C_SMEM_FLOATS (C_UO + 1024)           // 47104 floats = 188416 B

__global__ void __launch_bounds__(C_THREADS, 1)
core_kernel(const float* __restrict__ G, const float* __restrict__ Uout,
            float* __restrict__ out, int n, int ntiles)
{
    extern __shared__ float sm2[];
    float* GsA = sm2 + C_GSA;
    float* GsB = sm2 + C_GSB;
    float* Uos = sm2 + C_UO;

    const int t = threadIdx.x;
    const int warp = t >> 5, lane = t & 31;
    float* wSw = sm2 + C_W + warp * C_WPER;
    float* rSw = wSw + 640;

    // stage G: gmem idx = j*512 + k  ->  GsA/GsB[k*32 + jg*4 + m]
    for (int idx = t; idx < 32768; idx += C_THREADS) {
        int j = idx >> 9, k = idx & 511;
        int jg = j >> 3, jm = j & 7;
        float v = G[idx];
        if (jm < 4) GsA[k * 32 + jg * 4 + jm] = v;
        else        GsB[k * 32 + jg * 4 + (jm - 4)] = v;
    }
    for (int idx = t; idx < 1024; idx += C_THREADS) Uos[idx] = Uout[idx];
    __syncthreads();

    const int jg = lane >> 2;    // 0..7 : 8 j's at jg*8 (4 j-pairs)
    const int ng = lane & 3;     // 0..3 : node-pair (ng*2, ng*2+1)
    const int nl = lane & 7;     // epilogue node
    const int q  = lane >> 3;    // epilogue output quarter

    const int a3b = lane >> 2;   // build role: a3 = lane>>2, nq = lane&3
    const int nqb = lane & 3;

    for (int tile = blockIdx.x * C_NW + warp; tile < ntiles;
         tile += gridDim.x * C_NW) {
        const int base = tile * 8;

        // stage this tile's ris factors r1,r2,r3 into rSw[24][8]
        if (lane < 8) {
            int nd = base + lane;
            int ok = nd < n;
            #pragma unroll
            for (int rr = 0; rr < 24; ++rr)
                rSw[rr * 8 + lane] = ok ? g_ris[(8 + rr) * MAX_N + nd] : 0.f;
        }
        // epilogue factors r0 (per lane, node = base+nl)
        float r0[8];
        {
            int nd = base + nl;
            int ok = nd < n;
            #pragma unroll
            for (int a = 0; a < 8; ++a)
                r0[a] = ok ? g_ris[a * MAX_N + nd] : 0.f;
        }
        __syncwarp();

        uint64_t acc[4][2];   // [j-pair][node-in-pair]
        #pragma unroll
        for (int a = 0; a < 4; ++a) { acc[a][0] = 0; acc[a][1] = 0; }

        #pragma unroll 1
        for (int c = 0; c < 8; ++c) {
            // ---- build w chunk (a2 = c) as packed node-pairs ----
            uint64_t r3p = *reinterpret_cast<const unsigned long long*>(
                rSw + (16 + c) * 8 + nqb * 2);
            uint64_t r2p = *reinterpret_cast<const unsigned long long*>(
                rSw + (8 + a3b) * 8 + nqb * 2);
            uint64_t p23; MUL_F32X2(p23, r3p, r2p);
            #pragma unroll
            for (int a4 = 0; a4 < 8; ++a4) {
                uint64_t r1p = *reinterpret_cast<const unsigned long long*>(
                    rSw + a4 * 8 + nqb * 2);
                uint64_t w2; MUL_F32X2(w2, p23, r1p);
                *reinterpret_cast<unsigned long long*>(
                    wSw + (a3b * 8 + a4) * 10 + nqb * 2) = w2;
            }
            __syncwarp();

            // ---- GEMM over 64-k chunk ----
            const float* gpA = GsA + (c * 64) * 32 + jg * 4;
            const float* gpB = GsB + (c * 64) * 32 + jg * 4;
            const float* wp  = wSw + ng * 2;
            ulonglong2 ga = *reinterpret_cast<const ulonglong2*>(gpA);
            ulonglong2 gb = *reinterpret_cast<const ulonglong2*>(gpB);
            float2     wv = *reinterpret_cast<const float2*>(wp);
            #pragma unroll 4
            for (int kc = 0; kc < 64; ++kc) {
                ulonglong2 cga = ga, cgb = gb;
                float2 cwv = wv;
                if (kc + 1 < 64) {
                    ga = *reinterpret_cast<const ulonglong2*>(gpA + (kc + 1) * 32);
                    gb = *reinterpret_cast<const ulonglong2*>(gpB + (kc + 1) * 32);
                    wv = *reinterpret_cast<const float2*>(wp + (kc + 1) * 10);
                }
                uint64_t w0, w1;
                DUP_F32(w0, __float_as_uint(cwv.x));
                DUP_F32(w1, __float_as_uint(cwv.y));
                FMA_F32X2(acc[0][0], cga.x, w0); FMA_F32X2(acc[0][1], cga.x, w1);
                FMA_F32X2(acc[1][0], cga.y, w0); FMA_F32X2(acc[1][1], cga.y, w1);
                FMA_F32X2(acc[2][0], cgb.x, w0); FMA_F32X2(acc[2][1], cgb.x, w1);
                FMA_F32X2(acc[3][0], cgb.y, w0); FMA_F32X2(acc[3][1], cgb.y, w1);
            }
            __syncwarp();   // before next chunk's build overwrites wSw
        }

        // ---- write T[n_local][j] into wSw (stride 66) ----
        #pragma unroll
        for (int jp = 0; jp < 4; ++jp) {
            #pragma unroll
            for (int nn = 0; nn < 2; ++nn) {
                *reinterpret_cast<unsigned long long*>(
                    wSw + (ng * 2 + nn) * 66 + jg * 8 + 2 * jp) = acc[jp][nn];
            }
        }
        __syncwarp();

        // ---- epilogue: lane -> (node = base+nl, output cols q*4 + m*16) ----
        {
            int nd = base + nl;
            if (nd < n) {
                const float* Trow = wSw + nl * 66;
                float s[8];
                #pragma unroll
                for (int a1 = 0; a1 < 8; ++a1) {
                    float sv = 0.f;
                    #pragma unroll
                    for (int a0 = 0; a0 < 8; ++a0)
                        sv = fmaf(Trow[a0 * 8 + a1], r0[a0], sv);
                    s[a1] = sv;
                }
                float* orow = out + (size_t)nd * 128;
                #pragma unroll
                for (int m = 0; m < 8; ++m) {
                    int o = q * 4 + m * 16;
                    float4 ov = make_float4(0.f, 0.f, 0.f, 0.f);
                    #pragma unroll
                    for (int a1 = 0; a1 < 8; ++a1) {
                        float sv = s[a1];
                        float4 uv = *reinterpret_cast<const float4*>(Uos + a1 * 128 + o);
                        ov.x = fmaf(sv, uv.x, ov.x);
                        ov.y = fmaf(sv, uv.y, ov.y);
                        ov.z = fmaf(sv, uv.z, ov.z);
                        ov.w = fmaf(sv, uv.w, ov.w);
                    }
                    *reinterpret_cast<float4*>(orow + o) = ov;
                }
            }
        }
        __syncwarp();   // before next tile's rSw/wSw writes
    }
}

// ================= launch =================
extern "C" void kernel_launch(void* const* d_in, const int* in_sizes, int n_in,
                              void* d_out, int out_size)
{
    const float* x  = (const float*)d_in[0];   // [N,4,256]
    const float* G  = (const float*)d_in[1];   // [8,8,8,8,8]
    const float* Us = (const float*)d_in[2];   // [4,256,8]
    const float* Uo = (const float*)d_in[3];   // [8,128]
    float* out = (float*)d_out;                // [N,128]

    int n = in_sizes[0] / 1024;
    if (n < 0) n = 0;
    if (n > MAX_N) n = MAX_N;
    int nblk1  = (n + R_TILE - 1) / R_TILE;
    int ntiles = (n + 7) / 8;
    if (ntiles == 0) return;

    cudaFuncSetAttribute(ris_kernel,  cudaFuncAttributeMaxDynamicSharedMemorySize,
                         R_SMEM_FLOATS * 4);
    cudaFuncSetAttribute(core_kernel, cudaFuncAttributeMaxDynamicSharedMemorySize,
                         C_SMEM_FLOATS * 4);

    int nsm = 148;
    cudaDeviceGetAttribute(&nsm, cudaDevAttrMultiProcessorCount, 0);
    int needed = (ntiles + C_NW - 1) / C_NW;
    int grid2 = (nsm < needed) ? nsm : needed;

    ris_kernel<<<nblk1, R_THREADS, R_SMEM_FLOATS * 4>>>(x, Us, n);
    core_kernel<<<grid2, C_THREADS, C_SMEM_FLOATS * 4>>>(G, Uo, out, n, ntiles);
}